// round 14
// baseline (speedup 1.0000x reference)
#include <cuda_runtime.h>
#include <math.h>

#define Bn 4
#define Cn 32
#define On 32
#define MD 12
#define MHW 24

__device__ float2 g_X1[Bn*Cn*64*MD*64];
__device__ float2 g_X3[Bn*Cn*MD*MHW*MHW];
__device__ float2 g_Y [Bn*On*MD*MHW*MHW];
__device__ float2 g_Z1[Bn*On*64*MD*MHW];
__device__ float  g_CFTP[8][256][576];
__device__ float  g_CORR[Bn*On*64];

__device__ __forceinline__ double ffma2(double a, double b, double c) {
    unsigned long long r;
    asm("fma.rn.f32x2 %0, %1, %2, %3;" : "=l"(r)
        : "l"(__double_as_longlong(a)), "l"(__double_as_longlong(b)), "l"(__double_as_longlong(c)));
    return __longlong_as_double(r);
}
__device__ __forceinline__ double add2(double a, double b) {
    unsigned long long r;
    asm("add.rn.f32x2 %0, %1, %2;" : "=l"(r)
        : "l"(__double_as_longlong(a)), "l"(__double_as_longlong(b)));
    return __longlong_as_double(r);
}
__device__ __forceinline__ double pk(float lo, float hi) {
    return __hiloint2double(__float_as_int(hi), __float_as_int(lo));
}
__device__ __forceinline__ float plo(double d) { return __int_as_float(__double2loint(d)); }
__device__ __forceinline__ float phi(double d) { return __int_as_float(__double2hiint(d)); }
__device__ __forceinline__ void initE(float2* E, int t, int nthr) {
    for (int i = t; i < 64; i += nthr)
        E[i] = make_float2(cospif(i * (1.0f/32.0f)), sinpif(i * (1.0f/32.0f)));
}

// F1: real DFT along D, packed over adjacent w-pairs. grid 4096 (2 rows), 128 thr
__global__ void __launch_bounds__(128) k_f1(const float* __restrict__ x) {
    __shared__ float xt[2*4352];          // [hh][d*68 + w], 68-pad for 16B alignment
    __shared__ double2 Et[64];
    int t = threadIdx.x;
    if (t < 64) {
        float c = cospif(t*(1.0f/32.0f)), s = sinpif(t*(1.0f/32.0f));
        Et[t] = make_double2(pk(c,c), pk(-s,-s));
    }
    const float4* xr4 = (const float4*)(x + (size_t)blockIdx.x * 8192);
    for (int i = t; i < 2048; i += 128) {
        float4 v = xr4[i];
        int hh = i >> 10, r = i & 1023;
        int w = r >> 4, d0 = (r & 15) * 4;
        float* base = &xt[hh*4352 + w];
        base[(d0  )*68] = v.x;
        base[(d0+1)*68] = v.y;
        base[(d0+2)*68] = v.z;
        base[(d0+3)*68] = v.w;
    }
    __syncthreads();
    // thread -> (hh, jg, wq): 4 adjacent w = wq*4..wq*4+3, 3 kd = jg*3..jg*3+2
    int hh = t >> 6, jg = (t >> 4) & 3, wq = t & 15, kd0 = jg*3;
    const float* xrow = &xt[hh*4352];
    double ar[2][3], ai[2][3];
    #pragma unroll
    for (int p = 0; p < 2; p++)
        #pragma unroll
        for (int u = 0; u < 3; u++) { ar[p][u]=0; ai[p][u]=0; }
    int i0=0, i1=0, i2=0;
    int s0=kd0*16, s1=s0+16, s2=s0+32;
    #pragma unroll 4
    for (int d = 0; d < 64; d++) {
        double2 e0 = *(const double2*)((const char*)Et + i0);
        double2 e1 = *(const double2*)((const char*)Et + i1);
        double2 e2 = *(const double2*)((const char*)Et + i2);
        i0=(i0+s0)&1023; i1=(i1+s1)&1023; i2=(i2+s2)&1023;
        double2 xv2 = *(const double2*)&xrow[d*68 + wq*4];   // 4 w's, 16B aligned
        #pragma unroll
        for (int p = 0; p < 2; p++) {
            double xv = p ? xv2.y : xv2.x;
            ar[p][0]=ffma2(xv,e0.x,ar[p][0]); ai[p][0]=ffma2(xv,e0.y,ai[p][0]);
            ar[p][1]=ffma2(xv,e1.x,ar[p][1]); ai[p][1]=ffma2(xv,e1.y,ai[p][1]);
            ar[p][2]=ffma2(xv,e2.x,ar[p][2]); ai[p][2]=ffma2(xv,e2.y,ai[p][2]);
        }
    }
    double* o = (double*)g_X1 + (size_t)(blockIdx.x*2 + hh) * 768;
    #pragma unroll
    for (int p = 0; p < 2; p++) {
        int w0 = wq*4 + p*2;
        #pragma unroll
        for (int u = 0; u < 3; u++) {
            o[(kd0+u)*64 + w0  ] = pk(plo(ar[p][u]), plo(ai[p][u]));
            o[(kd0+u)*64 + w0+1] = pk(phi(ar[p][u]), phi(ai[p][u]));
        }
    }
}

// F23: fused DFT W + H (proven 52us version). grid 1536=(bc,kd), 320 thr
__global__ void __launch_bounds__(320) k_f23() {
    __shared__ double A[4160];
    __shared__ float B2r[1560], B2i[1560];
    __shared__ double2 T2[64];
    __shared__ float2 E[64];
    int t = threadIdx.x;
    if (t < 64) {
        float c = cospif(t*(1.0f/32.0f)), s = sinpif(t*(1.0f/32.0f));
        T2[t] = make_double2(pk(c,c), pk(s,s));
        E[t] = make_float2(c, s);
    }
    int bc = blockIdx.x / 12, kd = blockIdx.x % 12;
    const double* src = (const double*)g_X1 + (size_t)bc*64*768 + kd*64;
    for (int i = t; i < 4096; i += 320)
        A[(i&63)*65 + (i>>6)] = src[(size_t)(i>>6)*768 + (i&63)];
    __syncthreads();
    if (t < 256) {
        int h = t & 63, g = t >> 6;
        int p0 = g*3 + 1;
        double aA[3] = {0,0,0}, aB[3] = {0,0,0}, acc0 = 0;
        int idx[3], stp[3];
        #pragma unroll
        for (int u = 0; u < 3; u++) { stp[u] = (p0+u)*16; idx[u] = 0; }
        #pragma unroll 4
        for (int w = 0; w < 64; w++) {
            double a = A[w*65+h];
            if (g == 0) acc0 = add2(acc0, a);
            #pragma unroll
            for (int u = 0; u < 3; u++) {
                double2 e = *(const double2*)((const char*)T2 + idx[u]);
                idx[u] = (idx[u] + stp[u]) & 1023;
                aA[u] = ffma2(a, e.x, aA[u]);
                aB[u] = ffma2(a, e.y, aB[u]);
            }
        }
        #pragma unroll
        for (int u = 0; u < 3; u++) {
            int p = p0 + u;
            float Ax = plo(aA[u]), Cx = phi(aA[u]);
            float Dx = plo(aB[u]), Bx = phi(aB[u]);
            if (p < 12) {
                B2r[p*65+h]      = Ax+Bx;  B2i[p*65+h]      = Cx-Dx;
                B2r[(24-p)*65+h] = Ax-Bx;  B2i[(24-p)*65+h] = Cx+Dx;
            } else {
                B2r[12*65+h]     = Ax-Bx;  B2i[12*65+h]     = Cx+Dx;
            }
        }
        if (g == 0) { B2r[h] = plo(acc0); B2i[h] = phi(acc0); }
    }
    __syncthreads();
    if (t < 312) {
        int kw = t % 24, pp = t / 24;
        float2* o = g_X3 + (size_t)(bc*12 + kd)*576;
        if (pp < 12) {
            int p = pp + 1;
            float Ax=0, Bx=0, Cx=0, Dx=0;
            int ei = 0, es = (p*8) & 511;
            #pragma unroll 4
            for (int h = 0; h < 64; h++) {
                float ax = B2r[kw*65+h], ay = B2i[kw*65+h];
                float2 e = *(const float2*)((const char*)E + ei);
                ei = (ei + es) & 511;
                Ax = fmaf(ax, e.x, Ax); Dx = fmaf(ax, e.y, Dx);
                Cx = fmaf(ay, e.x, Cx); Bx = fmaf(ay, e.y, Bx);
            }
            if (p < 12) {
                o[p*24 + kw]      = make_float2(Ax+Bx, Cx-Dx);
                o[(24-p)*24 + kw] = make_float2(Ax-Bx, Cx+Dx);
            } else {
                o[12*24 + kw]     = make_float2(Ax-Bx, Cx+Dx);
            }
        } else {
            float r = 0, im = 0;
            #pragma unroll 4
            for (int h = 0; h < 64; h++) { r += B2r[kw*65+h]; im += B2i[kw*65+h]; }
            o[kw] = make_float2(r, im);
        }
    }
}

// MIX. grid 576, 256 thr, dyn smem 110592
__global__ void __launch_bounds__(256) k_mix(
        const float* __restrict__ w1re, const float* __restrict__ w1im,
        const float* __restrict__ w2re, const float* __restrict__ w2im,
        const float* __restrict__ w3re, const float* __restrict__ w3im,
        const float* __restrict__ w4re, const float* __restrict__ w4im) {
    extern __shared__ float sm[];
    float*  Wre = sm;
    float*  Wim = sm + 12288;
    float2* X3s = (float2*)(sm + 24576);
    const float* wres[4] = {w1re, w2re, w3re, w4re};
    const float* wims[4] = {w1im, w2im, w3im, w4im};
    int t = threadIdx.x;
    int q = blockIdx.x / 144, mm = blockIdx.x % 144;
    int m1 = mm / 12, m2 = mm % 12;
    int mhw = (m1 + (q&1)*12)*24 + m2 + ((q>>1)&1)*12;
    const float* wre = wres[q];
    const float* wim = wims[q];
    int woff = m1*144 + m2*12;
    for (int idx = t; idx < 3072; idx += 256) {
        int io = idx / 3, r3 = idx - io*3;
        size_t g = (size_t)io*1728 + woff + r3*4;
        float4 vr = *(const float4*)(wre + g);
        float4 vi = *(const float4*)(wim + g);
        int sl = ((io>>5)*12 + r3*4)*32 + (io&31);
        Wre[sl] = vr.x; Wre[sl+32] = vr.y; Wre[sl+64] = vr.z; Wre[sl+96] = vr.w;
        Wim[sl] = vi.x; Wim[sl+32] = vi.y; Wim[sl+64] = vi.z; Wim[sl+96] = vi.w;
    }
    for (int idx = t; idx < 1536; idx += 256)
        X3s[idx] = g_X3[(size_t)idx*576 + mhw];
    __syncthreads();
    int o = t & 31, b = (t >> 5) & 3, kdh = t >> 7;
    float2 acc[6];
    #pragma unroll
    for (int u = 0; u < 6; u++) acc[u] = make_float2(0,0);
    for (int i = 0; i < 32; i++) {
        int xb = (b*32+i)*12 + kdh*6, wb = i*384 + kdh*192 + o;
        #pragma unroll
        for (int u = 0; u < 6; u++) {
            float2 a = X3s[xb+u];
            float wr = Wre[wb+u*32], wi = Wim[wb+u*32];
            acc[u].x = fmaf(a.x,wr,fmaf(-a.y,wi,acc[u].x));
            acc[u].y = fmaf(a.x,wi,fmaf( a.y,wr,acc[u].y));
        }
    }
    #pragma unroll
    for (int u = 0; u < 6; u++)
        g_Y[((size_t)(b*32+o)*12 + kdh*6+u)*576 + mhw] = acc[u];
}

// I1: inverse DFT along H, paired. grid 1536, 256 thr
__global__ void __launch_bounds__(256) k_i1() {
    __shared__ double Yp[264], Ym[264];
    __shared__ double Y0[24], Y52a[24], Y52b[24];
    __shared__ float2 E[64];
    int t = threadIdx.x;
    initE(E, t, 256);
    int bo = blockIdx.x / 12, kd = blockIdx.x % 12;
    const float2* Yr = g_Y + (size_t)(bo*12+kd)*576;
    for (int i = t; i < 312; i += 256) {
        if (i < 264) {
            int p = i/24 + 1, kw = i % 24;
            float2 z1 = Yr[p*24 + kw], z2 = Yr[(24-p)*24 + kw];
            Yp[i] = pk(z1.x + z2.x, z1.y + z2.y);
            Ym[i] = pk(z2.y - z1.y, z1.x - z2.x);
        } else if (i < 288) {
            int kw = i - 264;
            float2 z = Yr[kw];
            Y0[kw] = pk(z.x, z.y);
        } else {
            int kw = i - 288;
            float2 z = Yr[12*24 + kw];
            Y52a[kw] = pk(z.x, z.y);
            Y52b[kw] = pk(-z.y, z.x);
        }
    }
    __syncthreads();
    int h = t & 63, kwg = t >> 6;
    int kw0 = kwg * 6;
    double acc[6];
    #pragma unroll
    for (int u = 0; u < 6; u++) acc[u] = Y0[kw0+u];
    int ei = (h*8) & 511, es = h*8;
    for (int p = 1; p <= 11; p++) {
        float2 ef = *(const float2*)((const char*)E + ei);
        ei = (ei + es) & 511;
        double ex = pk(ef.x, ef.x), ey = pk(ef.y, ef.y);
        int base = (p-1)*24 + kw0;
        #pragma unroll
        for (int u = 0; u < 6; u++) {
            acc[u] = ffma2(Yp[base+u], ex, acc[u]);
            acc[u] = ffma2(Ym[base+u], ey, acc[u]);
        }
    }
    float2 e52f = E[(52*h) & 63];
    double e52x = pk(e52f.x, e52f.x), e52y = pk(e52f.y, e52f.y);
    #pragma unroll
    for (int u = 0; u < 6; u++) {
        acc[u] = ffma2(Y52a[kw0+u], e52x, acc[u]);
        acc[u] = ffma2(Y52b[kw0+u], e52y, acc[u]);
    }
    double* o = (double*)g_Z1 + ((size_t)(bo*64+h)*12 + kd)*24 + kw0;
    #pragma unroll
    for (int u = 0; u < 6; u++) o[u] = acc[u];
}

// I23: fused inverse W (paired, p-pair LDS.128) + real inverse D + corr. grid 8192, 256 thr
__global__ void __launch_bounds__(256) k_i23(float* __restrict__ out) {
    __shared__ __align__(16) double Zp[144], Zm[144];   // [kd*12 + (p-1)], padded
    __shared__ double Z0[12], Z52a[12], Z52b[12];
    __shared__ __align__(16) double Zw[768];
    __shared__ float2 E[64];
    int t = threadIdx.x;
    initE(E, t, 256);
    size_t boh = blockIdx.x;
    const float2* src = g_Z1 + boh*288;
    for (int i = t; i < 144; i += 256) {
        int kd = i / 12, pp = i % 12;
        if (pp < 11) {
            int p = pp + 1;
            float2 z1 = src[kd*24 + p], z2 = src[kd*24 + 24 - p];
            Zp[kd*12 + pp] = pk(z1.x + z2.x, z1.y + z2.y);
            Zm[kd*12 + pp] = pk(z2.y - z1.y, z1.x - z2.x);
        } else {
            Zp[kd*12 + 11] = 0.0;
            Zm[kd*12 + 11] = 0.0;
            float2 z0 = src[kd*24];
            Z0[kd] = pk(z0.x, z0.y);
            float2 zc = src[kd*24 + 12];
            Z52a[kd] = pk(zc.x, zc.y);
            Z52b[kd] = pk(-zc.y, zc.x);
        }
    }
    __syncthreads();
    {
        int w = t & 63, kdg = t >> 6;
        double acc[3];
        #pragma unroll
        for (int u = 0; u < 3; u++) acc[u] = Z0[kdg*3+u];
        int ei = (w*8) & 511, es = w*8;
        // p-pairs: (1,2),(3,4),...,(11,pad)
        #pragma unroll 2
        for (int pp = 0; pp < 6; pp++) {
            float2 ef0 = *(const float2*)((const char*)E + ei);
            ei = (ei + es) & 511;
            float2 ef1 = *(const float2*)((const char*)E + ei);
            ei = (ei + es) & 511;
            double ex0 = pk(ef0.x, ef0.x), ey0 = pk(ef0.y, ef0.y);
            double ex1 = pk(ef1.x, ef1.x), ey1 = pk(ef1.y, ef1.y);
            #pragma unroll
            for (int u = 0; u < 3; u++) {
                int base = (kdg*3+u)*12 + pp*2;
                double2 zp = *(const double2*)&Zp[base];
                double2 zm = *(const double2*)&Zm[base];
                acc[u] = ffma2(zp.x, ex0, acc[u]);
                acc[u] = ffma2(zm.x, ey0, acc[u]);
                acc[u] = ffma2(zp.y, ex1, acc[u]);
                acc[u] = ffma2(zm.y, ey1, acc[u]);
            }
        }
        float2 e52f = E[(52*w) & 63];
        double e52x = pk(e52f.x, e52f.x), e52y = pk(e52f.y, e52f.y);
        #pragma unroll
        for (int u = 0; u < 3; u++) {
            acc[u] = ffma2(Z52a[kdg*3+u], e52x, acc[u]);
            acc[u] = ffma2(Z52b[kdg*3+u], e52y, acc[u]);
        }
        #pragma unroll
        for (int u = 0; u < 3; u++) Zw[w*12 + kdg*3+u] = acc[u];
    }
    __syncthreads();
    int d = t & 63, wg = t >> 6;
    int b = blockIdx.x >> 11, o = (blockIdx.x >> 6) & 31;
    float cv = g_CORR[(b*32+o)*64 + d];
    const float SC = 1.0f/262144.0f;
    double F2[12];
    F2[0] = pk(1.f, 0.f);
    #pragma unroll
    for (int k = 1; k <= 11; k++) {
        float2 e = E[(k*d)&63];
        F2[k] = pk(2.f*e.x, -2.f*e.y);
    }
    float* orow = out + boh*4096;
    #pragma unroll 2
    for (int j = 0; j < 16; j++) {
        int w = wg*16 + j;
        const double2* z2 = (const double2*)&Zw[w*12];
        double acc = 0;
        #pragma unroll
        for (int m = 0; m < 6; m++) {
            double2 zz = z2[m];
            acc = ffma2(zz.x, F2[2*m], acc);
            acc = ffma2(zz.y, F2[2*m+1], acc);
        }
        orow[w*64 + d] = fmaf(SC, plo(acc) + phi(acc), cv);
    }
}

// CK1: per-segment partials, packed. grid 256 = (b,dc,s), 256 thr
__global__ void k_ck1(const float* __restrict__ x) {
    __shared__ double2 Ed[64];
    int t = threadIdx.x;
    if (t < 64) {
        float c1 = cospif(t*(1.0f/32.0f)), s1 = sinpif(t*(1.0f/32.0f));
        int w2 = (2*t) & 63;
        float c2 = cospif(w2*(1.0f/32.0f)), s2 = sinpif(w2*(1.0f/32.0f));
        Ed[t] = make_double2(pk(c1,-s1), pk(c2,-s2));
    }
    __syncthreads();
    int bid = blockIdx.x;
    int b = bid >> 6, dc = (bid >> 3) & 7, s = bid & 7;
    int c = t >> 3, d = dc*8 + (t & 7);
    float ts = -1.0f + (2.0f/7.0f)*s;
    float p1 = ts, p2 = 2.0f*ts*ts - 1.0f;
    double a1 = 0, a2 = 0, a4 = 0, a5 = 0, a7 = 0, a8 = 0;
    double dc01 = 0;
    float ar6 = 0;
    const float* base = x + ((size_t)(b*32+c)*64 + s)*4096 + d;
    #pragma unroll 4
    for (int w = 0; w < 64; w++) {
        float xv = base[w*64];
        double2 e = Ed[w];
        float m1 = xv*p1, m2 = xv*p2;
        double d0 = pk(xv, xv), d1 = pk(m1, m1), d2 = pk(m2, m2);
        dc01 = add2(dc01, pk(xv, m1));
        ar6 += m2;
        a1 = ffma2(d0, e.x, a1);  a2 = ffma2(d0, e.y, a2);
        a4 = ffma2(d1, e.x, a4);  a5 = ffma2(d1, e.y, a5);
        a7 = ffma2(d2, e.x, a7);  a8 = ffma2(d2, e.y, a8);
    }
    float* dst = &g_CFTP[s][b*64+d][c*18];
    dst[0]  = plo(dc01)*0.125f; dst[1]  = 0.f;
    dst[2]  = plo(a1)*0.125f;   dst[3]  = phi(a1)*0.125f;
    dst[4]  = plo(a2)*0.125f;   dst[5]  = phi(a2)*0.125f;
    dst[6]  = phi(dc01)*0.125f; dst[7]  = 0.f;
    dst[8]  = plo(a4)*0.125f;   dst[9]  = phi(a4)*0.125f;
    dst[10] = plo(a5)*0.125f;   dst[11] = phi(a5)*0.125f;
    dst[12] = ar6*0.125f;       dst[13] = 0.f;
    dst[14] = plo(a7)*0.125f;   dst[15] = phi(a7)*0.125f;
    dst[16] = plo(a8)*0.125f;   dst[17] = phi(a8)*0.125f;
}

// CK2: sum partials + MLP. grid 256, 128 thr
__global__ void k_ck2(const float* __restrict__ W1, const float* __restrict__ b1,
                      const float* __restrict__ W2, const float* __restrict__ b2,
                      const float* __restrict__ corr_scale) {
    __shared__ float fl[576];
    __shared__ float hb[128];
    int n = blockIdx.x, t = threadIdx.x;
    for (int i = t; i < 576; i += 128) {
        float v = 0;
        #pragma unroll
        for (int s = 0; s < 8; s++) v += g_CFTP[s][n][i];
        fl[i] = v;
    }
    __syncthreads();
    float acc = b1[t];
    #pragma unroll 4
    for (int k = 0; k < 576; k++)
        acc = fmaf(fl[k], W1[(size_t)k*128 + t], acc);
    hb[t] = 0.5f*acc*(1.0f + erff(acc*0.70710678118654752f));
    __syncthreads();
    if (t < 32) {
        float a2 = b2[t];
        #pragma unroll 4
        for (int k = 0; k < 128; k++)
            a2 = fmaf(hb[k], W2[k*32 + t], a2);
        g_CORR[((n>>6)*32 + t)*64 + (n&63)] = a2*corr_scale[0];
    }
}

extern "C" void kernel_launch(void* const* d_in, const int* in_sizes, int n_in,
                              void* d_out, int out_size) {
    const float* x    = (const float*)d_in[0];
    const float* w1re = (const float*)d_in[1];
    const float* w1im = (const float*)d_in[2];
    const float* w2re = (const float*)d_in[3];
    const float* w2im = (const float*)d_in[4];
    const float* w3re = (const float*)d_in[5];
    const float* w3im = (const float*)d_in[6];
    const float* w4re = (const float*)d_in[7];
    const float* w4im = (const float*)d_in[8];
    const float* W1   = (const float*)d_in[9];
    const float* b1   = (const float*)d_in[10];
    const float* W2   = (const float*)d_in[11];
    const float* b2   = (const float*)d_in[12];
    const float* cs   = (const float*)d_in[13];
    float* out = (float*)d_out;

    static int smem_set = 0;
    const int mix_smem = 110592;
    if (!smem_set) {
        cudaFuncSetAttribute(k_mix, cudaFuncAttributeMaxDynamicSharedMemorySize, mix_smem);
        smem_set = 1;
    }

    k_ck1<<<256, 256>>>(x);
    k_ck2<<<256, 128>>>(W1, b1, W2, b2, cs);

    k_f1<<<4096, 128>>>(x);
    k_f23<<<1536, 320>>>();
    k_mix<<<576, 256, mix_smem>>>(w1re, w1im, w2re, w2im, w3re, w3im, w4re, w4im);
    k_i1<<<1536, 256>>>();
    k_i23<<<8192, 256>>>(out);
}

// round 15
// speedup vs baseline: 1.0496x; 1.0496x over previous
#include <cuda_runtime.h>
#include <math.h>

#define Bn 4
#define Cn 32
#define On 32
#define MD 12
#define MHW 24

__device__ float2 g_X1[Bn*Cn*64*MD*64];
__device__ float2 g_X3[Bn*Cn*MD*MHW*MHW];
__device__ float2 g_Y [Bn*On*MD*MHW*MHW];
__device__ float2 g_Z1[Bn*On*64*MD*MHW];
__device__ float  g_CFTP[8][256][576];
__device__ float  g_CORR[Bn*On*64];

__device__ __forceinline__ double ffma2(double a, double b, double c) {
    unsigned long long r;
    asm("fma.rn.f32x2 %0, %1, %2, %3;" : "=l"(r)
        : "l"(__double_as_longlong(a)), "l"(__double_as_longlong(b)), "l"(__double_as_longlong(c)));
    return __longlong_as_double(r);
}
__device__ __forceinline__ double add2(double a, double b) {
    unsigned long long r;
    asm("add.rn.f32x2 %0, %1, %2;" : "=l"(r)
        : "l"(__double_as_longlong(a)), "l"(__double_as_longlong(b)));
    return __longlong_as_double(r);
}
__device__ __forceinline__ double pk(float lo, float hi) {
    return __hiloint2double(__float_as_int(hi), __float_as_int(lo));
}
__device__ __forceinline__ float plo(double d) { return __int_as_float(__double2loint(d)); }
__device__ __forceinline__ float phi(double d) { return __int_as_float(__double2hiint(d)); }
__device__ __forceinline__ void initE(float2* E, int t, int nthr) {
    for (int i = t; i < 64; i += nthr)
        E[i] = make_float2(cospif(i * (1.0f/32.0f)), sinpif(i * (1.0f/32.0f)));
}

// F1: real DFT along D, packed over w-pairs. grid 4096, 128 thr (R12 exact)
__global__ void __launch_bounds__(128) k_f1(const float* __restrict__ x) {
    __shared__ float xt[2*4224];
    __shared__ double2 Et[64];
    int t = threadIdx.x;
    if (t < 64) {
        float c = cospif(t*(1.0f/32.0f)), s = sinpif(t*(1.0f/32.0f));
        Et[t] = make_double2(pk(c,c), pk(-s,-s));
    }
    const float4* xr4 = (const float4*)(x + (size_t)blockIdx.x * 8192);
    for (int i = t; i < 2048; i += 128) {
        float4 v = xr4[i];
        int hh = i >> 10, r = i & 1023;
        int w = r >> 4, d0 = (r & 15) * 4;
        float* base = &xt[hh*4224 + w];
        base[(d0  )*66] = v.x;
        base[(d0+1)*66] = v.y;
        base[(d0+2)*66] = v.z;
        base[(d0+3)*66] = v.w;
    }
    __syncthreads();
    int hh = t >> 6, jg = (t >> 4) & 3, wp0 = t & 15, kd0 = jg*3;
    const float* xrow = &xt[hh*4224];
    double ar[2][3], ai[2][3];
    #pragma unroll
    for (int p = 0; p < 2; p++)
        #pragma unroll
        for (int u = 0; u < 3; u++) { ar[p][u]=0; ai[p][u]=0; }
    int i0=0, i1=0, i2=0;
    int s0=kd0*16, s1=s0+16, s2=s0+32;
    #pragma unroll 4
    for (int d = 0; d < 64; d++) {
        double2 e0 = *(const double2*)((const char*)Et + i0);
        double2 e1 = *(const double2*)((const char*)Et + i1);
        double2 e2 = *(const double2*)((const char*)Et + i2);
        i0=(i0+s0)&1023; i1=(i1+s1)&1023; i2=(i2+s2)&1023;
        #pragma unroll
        for (int p = 0; p < 2; p++) {
            double xv = *(const double*)&xrow[d*66 + (wp0 + p*16)*2];
            ar[p][0]=ffma2(xv,e0.x,ar[p][0]); ai[p][0]=ffma2(xv,e0.y,ai[p][0]);
            ar[p][1]=ffma2(xv,e1.x,ar[p][1]); ai[p][1]=ffma2(xv,e1.y,ai[p][1]);
            ar[p][2]=ffma2(xv,e2.x,ar[p][2]); ai[p][2]=ffma2(xv,e2.y,ai[p][2]);
        }
    }
    double* o = (double*)g_X1 + (size_t)(blockIdx.x*2 + hh) * 768;
    #pragma unroll
    for (int p = 0; p < 2; p++) {
        int w0 = (wp0 + p*16)*2;
        #pragma unroll
        for (int u = 0; u < 3; u++) {
            o[(kd0+u)*64 + w0  ] = pk(plo(ar[p][u]), plo(ai[p][u]));
            o[(kd0+u)*64 + w0+1] = pk(phi(ar[p][u]), phi(ai[p][u]));
        }
    }
}

// F23: fused DFT W + H (R12 compute, double2 staging). grid 1536=(bc,kd), 320 thr
__global__ void __launch_bounds__(320) k_f23() {
    __shared__ double A[4160];            // [w*65+h]
    __shared__ float B2r[1560], B2i[1560];
    __shared__ double2 T2[64];
    __shared__ float2 E[64];
    int t = threadIdx.x;
    if (t < 64) {
        float c = cospif(t*(1.0f/32.0f)), s = sinpif(t*(1.0f/32.0f));
        T2[t] = make_double2(pk(c,c), pk(s,s));
        E[t] = make_float2(c, s);
    }
    int bc = blockIdx.x / 12, kd = blockIdx.x % 12;
    const double* src = (const double*)g_X1 + (size_t)bc*64*768 + kd*64;
    // staging: 2048 double2 items (h, wp): each thread loads 2 consecutive w
    for (int i = t; i < 2048; i += 320) {
        int h = i >> 5, wp = i & 31;
        double2 v = *(const double2*)&src[(size_t)h*768 + wp*2];
        A[(wp*2  )*65 + h] = v.x;
        A[(wp*2+1)*65 + h] = v.y;
    }
    __syncthreads();
    if (t < 256) {
        int h = t & 63, g = t >> 6;
        int p0 = g*3 + 1;
        double aA[3] = {0,0,0}, aB[3] = {0,0,0}, acc0 = 0;
        int idx[3], stp[3];
        #pragma unroll
        for (int u = 0; u < 3; u++) { stp[u] = (p0+u)*16; idx[u] = 0; }
        #pragma unroll 4
        for (int w = 0; w < 64; w++) {
            double a = A[w*65+h];
            if (g == 0) acc0 = add2(acc0, a);
            #pragma unroll
            for (int u = 0; u < 3; u++) {
                double2 e = *(const double2*)((const char*)T2 + idx[u]);
                idx[u] = (idx[u] + stp[u]) & 1023;
                aA[u] = ffma2(a, e.x, aA[u]);
                aB[u] = ffma2(a, e.y, aB[u]);
            }
        }
        #pragma unroll
        for (int u = 0; u < 3; u++) {
            int p = p0 + u;
            float Ax = plo(aA[u]), Cx = phi(aA[u]);
            float Dx = plo(aB[u]), Bx = phi(aB[u]);
            if (p < 12) {
                B2r[p*65+h]      = Ax+Bx;  B2i[p*65+h]      = Cx-Dx;
                B2r[(24-p)*65+h] = Ax-Bx;  B2i[(24-p)*65+h] = Cx+Dx;
            } else {
                B2r[12*65+h]     = Ax-Bx;  B2i[12*65+h]     = Cx+Dx;   // kw=52
            }
        }
        if (g == 0) { B2r[h] = plo(acc0); B2i[h] = phi(acc0); }        // kw=0
    }
    __syncthreads();
    if (t < 312) {
        int kw = t % 24, pp = t / 24;
        float2* o = g_X3 + (size_t)(bc*12 + kd)*576;
        if (pp < 12) {
            int p = pp + 1;
            float Ax=0, Bx=0, Cx=0, Dx=0;
            int ei = 0, es = (p*8) & 511;
            #pragma unroll 4
            for (int h = 0; h < 64; h++) {
                float ax = B2r[kw*65+h], ay = B2i[kw*65+h];
                float2 e = *(const float2*)((const char*)E + ei);
                ei = (ei + es) & 511;
                Ax = fmaf(ax, e.x, Ax); Dx = fmaf(ax, e.y, Dx);
                Cx = fmaf(ay, e.x, Cx); Bx = fmaf(ay, e.y, Bx);
            }
            if (p < 12) {
                o[p*24 + kw]      = make_float2(Ax+Bx, Cx-Dx);
                o[(24-p)*24 + kw] = make_float2(Ax-Bx, Cx+Dx);
            } else {
                o[12*24 + kw]     = make_float2(Ax-Bx, Cx+Dx);
            }
        } else {
            float r = 0, im = 0;
            #pragma unroll 4
            for (int h = 0; h < 64; h++) { r += B2r[kw*65+h]; im += B2i[kw*65+h]; }
            o[kw] = make_float2(r, im);
        }
    }
}

// MIX. grid 576, 256 thr, dyn smem 110592 (R12 exact)
__global__ void __launch_bounds__(256) k_mix(
        const float* __restrict__ w1re, const float* __restrict__ w1im,
        const float* __restrict__ w2re, const float* __restrict__ w2im,
        const float* __restrict__ w3re, const float* __restrict__ w3im,
        const float* __restrict__ w4re, const float* __restrict__ w4im) {
    extern __shared__ float sm[];
    float*  Wre = sm;
    float*  Wim = sm + 12288;
    float2* X3s = (float2*)(sm + 24576);
    const float* wres[4] = {w1re, w2re, w3re, w4re};
    const float* wims[4] = {w1im, w2im, w3im, w4im};
    int t = threadIdx.x;
    int q = blockIdx.x / 144, mm = blockIdx.x % 144;
    int m1 = mm / 12, m2 = mm % 12;
    int mhw = (m1 + (q&1)*12)*24 + m2 + ((q>>1)&1)*12;
    const float* wre = wres[q];
    const float* wim = wims[q];
    int woff = m1*144 + m2*12;
    for (int idx = t; idx < 3072; idx += 256) {
        int io = idx / 3, r3 = idx - io*3;
        size_t g = (size_t)io*1728 + woff + r3*4;
        float4 vr = *(const float4*)(wre + g);
        float4 vi = *(const float4*)(wim + g);
        int sl = ((io>>5)*12 + r3*4)*32 + (io&31);
        Wre[sl] = vr.x; Wre[sl+32] = vr.y; Wre[sl+64] = vr.z; Wre[sl+96] = vr.w;
        Wim[sl] = vi.x; Wim[sl+32] = vi.y; Wim[sl+64] = vi.z; Wim[sl+96] = vi.w;
    }
    for (int idx = t; idx < 1536; idx += 256)
        X3s[idx] = g_X3[(size_t)idx*576 + mhw];
    __syncthreads();
    int o = t & 31, b = (t >> 5) & 3, kdh = t >> 7;
    float2 acc[6];
    #pragma unroll
    for (int u = 0; u < 6; u++) acc[u] = make_float2(0,0);
    for (int i = 0; i < 32; i++) {
        int xb = (b*32+i)*12 + kdh*6, wb = i*384 + kdh*192 + o;
        #pragma unroll
        for (int u = 0; u < 6; u++) {
            float2 a = X3s[xb+u];
            float wr = Wre[wb+u*32], wi = Wim[wb+u*32];
            acc[u].x = fmaf(a.x,wr,fmaf(-a.y,wi,acc[u].x));
            acc[u].y = fmaf(a.x,wi,fmaf( a.y,wr,acc[u].y));
        }
    }
    #pragma unroll
    for (int u = 0; u < 6; u++)
        g_Y[((size_t)(b*32+o)*12 + kdh*6+u)*576 + mhw] = acc[u];
}

// I1: inverse DFT along H, paired; float4 staging. grid 1536, 256 thr
__global__ void __launch_bounds__(256) k_i1() {
    __shared__ double Yp[264], Ym[264];
    __shared__ double Y0[24], Y52a[24], Y52b[24];
    __shared__ float2 E[64];
    int t = threadIdx.x;
    initE(E, t, 256);
    int bo = blockIdx.x / 12, kd = blockIdx.x % 12;
    const float2* Yr = g_Y + (size_t)(bo*12+kd)*576;
    // staging: 132 kw-pair items + 24 extras
    for (int i = t; i < 156; i += 256) {
        if (i < 132) {
            int p = i/12 + 1, kwp = i % 12;       // kw pair = {2*kwp, 2*kwp+1}
            float4 z1 = *(const float4*)&Yr[p*24 + kwp*2];
            float4 z2 = *(const float4*)&Yr[(24-p)*24 + kwp*2];
            int base = (p-1)*24 + kwp*2;
            Yp[base  ] = pk(z1.x + z2.x, z1.y + z2.y);
            Ym[base  ] = pk(z2.y - z1.y, z1.x - z2.x);
            Yp[base+1] = pk(z1.z + z2.z, z1.w + z2.w);
            Ym[base+1] = pk(z2.w - z1.w, z1.z - z2.z);
        } else if (i < 144) {
            int kwp = i - 132;
            float4 z = *(const float4*)&Yr[kwp*2];
            Y0[kwp*2  ] = pk(z.x, z.y);
            Y0[kwp*2+1] = pk(z.z, z.w);
        } else {
            int kwp = i - 144;
            float4 z = *(const float4*)&Yr[12*24 + kwp*2];
            Y52a[kwp*2  ] = pk(z.x, z.y);
            Y52b[kwp*2  ] = pk(-z.y, z.x);
            Y52a[kwp*2+1] = pk(z.z, z.w);
            Y52b[kwp*2+1] = pk(-z.w, z.z);
        }
    }
    __syncthreads();
    int h = t & 63, kwg = t >> 6;
    int kw0 = kwg * 6;
    double acc[6];
    #pragma unroll
    for (int u = 0; u < 6; u++) acc[u] = Y0[kw0+u];
    int ei = (h*8) & 511, es = h*8;
    for (int p = 1; p <= 11; p++) {
        float2 ef = *(const float2*)((const char*)E + ei);
        ei = (ei + es) & 511;
        double ex = pk(ef.x, ef.x), ey = pk(ef.y, ef.y);
        int base = (p-1)*24 + kw0;
        #pragma unroll
        for (int u = 0; u < 6; u++) {
            acc[u] = ffma2(Yp[base+u], ex, acc[u]);
            acc[u] = ffma2(Ym[base+u], ey, acc[u]);
        }
    }
    float2 e52f = E[(52*h) & 63];
    double e52x = pk(e52f.x, e52f.x), e52y = pk(e52f.y, e52f.y);
    #pragma unroll
    for (int u = 0; u < 6; u++) {
        acc[u] = ffma2(Y52a[kw0+u], e52x, acc[u]);
        acc[u] = ffma2(Y52b[kw0+u], e52y, acc[u]);
    }
    double* o = (double*)g_Z1 + ((size_t)(bo*64+h)*12 + kd)*24 + kw0;
    #pragma unroll
    for (int u = 0; u < 6; u++) o[u] = acc[u];
}

// I23: fused inverse W (paired) + real inverse D + corr. grid 8192, 256 thr (R12 exact)
__global__ void __launch_bounds__(256) k_i23(float* __restrict__ out) {
    __shared__ double Zp[132], Zm[132];
    __shared__ double Z0[12], Z52a[12], Z52b[12];
    __shared__ __align__(16) double Zw[768];
    __shared__ float2 E[64];
    int t = threadIdx.x;
    initE(E, t, 256);
    size_t boh = blockIdx.x;
    const float2* src = g_Z1 + boh*288;
    for (int i = t; i < 144; i += 256) {
        if (i < 132) {
            int kd = i / 11, p = i % 11 + 1;
            float2 z1 = src[kd*24 + p], z2 = src[kd*24 + 24 - p];
            Zp[i] = pk(z1.x + z2.x, z1.y + z2.y);
            Zm[i] = pk(z2.y - z1.y, z1.x - z2.x);
        } else {
            int kd = i - 132;
            float2 z0 = src[kd*24];
            Z0[kd] = pk(z0.x, z0.y);
            float2 zc = src[kd*24 + 12];
            Z52a[kd] = pk(zc.x, zc.y);
            Z52b[kd] = pk(-zc.y, zc.x);
        }
    }
    __syncthreads();
    {
        int w = t & 63, kdg = t >> 6;
        double acc[3];
        #pragma unroll
        for (int u = 0; u < 3; u++) acc[u] = Z0[kdg*3+u];
        int ei = (w*8) & 511, es = w*8;
        for (int p = 1; p <= 11; p++) {
            float2 ef = *(const float2*)((const char*)E + ei);
            ei = (ei + es) & 511;
            double ex = pk(ef.x, ef.x), ey = pk(ef.y, ef.y);
            #pragma unroll
            for (int u = 0; u < 3; u++) {
                int idx = (kdg*3+u)*11 + p - 1;
                acc[u] = ffma2(Zp[idx], ex, acc[u]);
                acc[u] = ffma2(Zm[idx], ey, acc[u]);
            }
        }
        float2 e52f = E[(52*w) & 63];
        double e52x = pk(e52f.x, e52f.x), e52y = pk(e52f.y, e52f.y);
        #pragma unroll
        for (int u = 0; u < 3; u++) {
            acc[u] = ffma2(Z52a[kdg*3+u], e52x, acc[u]);
            acc[u] = ffma2(Z52b[kdg*3+u], e52y, acc[u]);
        }
        #pragma unroll
        for (int u = 0; u < 3; u++) Zw[w*12 + kdg*3+u] = acc[u];
    }
    __syncthreads();
    int d = t & 63, wg = t >> 6;
    int b = blockIdx.x >> 11, o = (blockIdx.x >> 6) & 31;
    float cv = g_CORR[(b*32+o)*64 + d];
    const float SC = 1.0f/262144.0f;
    double F2[12];
    F2[0] = pk(1.f, 0.f);
    #pragma unroll
    for (int k = 1; k <= 11; k++) {
        float2 e = E[(k*d)&63];
        F2[k] = pk(2.f*e.x, -2.f*e.y);
    }
    float* orow = out + boh*4096;
    #pragma unroll 2
    for (int j = 0; j < 16; j++) {
        int w = wg*16 + j;
        const double2* z2 = (const double2*)&Zw[w*12];
        double acc = 0;
        #pragma unroll
        for (int m = 0; m < 6; m++) {
            double2 zz = z2[m];
            acc = ffma2(zz.x, F2[2*m], acc);
            acc = ffma2(zz.y, F2[2*m+1], acc);
        }
        orow[w*64 + d] = fmaf(SC, plo(acc) + phi(acc), cv);
    }
}

// CK1: per-segment partials, packed. grid 256, 256 thr (R12 exact)
__global__ void k_ck1(const float* __restrict__ x) {
    __shared__ double2 Ed[64];
    int t = threadIdx.x;
    if (t < 64) {
        float c1 = cospif(t*(1.0f/32.0f)), s1 = sinpif(t*(1.0f/32.0f));
        int w2 = (2*t) & 63;
        float c2 = cospif(w2*(1.0f/32.0f)), s2 = sinpif(w2*(1.0f/32.0f));
        Ed[t] = make_double2(pk(c1,-s1), pk(c2,-s2));
    }
    __syncthreads();
    int bid = blockIdx.x;
    int b = bid >> 6, dc = (bid >> 3) & 7, s = bid & 7;
    int c = t >> 3, d = dc*8 + (t & 7);
    float ts = -1.0f + (2.0f/7.0f)*s;
    float p1 = ts, p2 = 2.0f*ts*ts - 1.0f;
    double a1 = 0, a2 = 0, a4 = 0, a5 = 0, a7 = 0, a8 = 0;
    double dc01 = 0;
    float ar6 = 0;
    const float* base = x + ((size_t)(b*32+c)*64 + s)*4096 + d;
    #pragma unroll 4
    for (int w = 0; w < 64; w++) {
        float xv = base[w*64];
        double2 e = Ed[w];
        float m1 = xv*p1, m2 = xv*p2;
        double d0 = pk(xv, xv), d1 = pk(m1, m1), d2 = pk(m2, m2);
        dc01 = add2(dc01, pk(xv, m1));
        ar6 += m2;
        a1 = ffma2(d0, e.x, a1);  a2 = ffma2(d0, e.y, a2);
        a4 = ffma2(d1, e.x, a4);  a5 = ffma2(d1, e.y, a5);
        a7 = ffma2(d2, e.x, a7);  a8 = ffma2(d2, e.y, a8);
    }
    float* dst = &g_CFTP[s][b*64+d][c*18];
    dst[0]  = plo(dc01)*0.125f; dst[1]  = 0.f;
    dst[2]  = plo(a1)*0.125f;   dst[3]  = phi(a1)*0.125f;
    dst[4]  = plo(a2)*0.125f;   dst[5]  = phi(a2)*0.125f;
    dst[6]  = phi(dc01)*0.125f; dst[7]  = 0.f;
    dst[8]  = plo(a4)*0.125f;   dst[9]  = phi(a4)*0.125f;
    dst[10] = plo(a5)*0.125f;   dst[11] = phi(a5)*0.125f;
    dst[12] = ar6*0.125f;       dst[13] = 0.f;
    dst[14] = plo(a7)*0.125f;   dst[15] = phi(a7)*0.125f;
    dst[16] = plo(a8)*0.125f;   dst[17] = phi(a8)*0.125f;
}

// CK2: sum partials + MLP. grid 256, 128 thr (R12 exact)
__global__ void k_ck2(const float* __restrict__ W1, const float* __restrict__ b1,
                      const float* __restrict__ W2, const float* __restrict__ b2,
                      const float* __restrict__ corr_scale) {
    __shared__ float fl[576];
    __shared__ float hb[128];
    int n = blockIdx.x, t = threadIdx.x;
    for (int i = t; i < 576; i += 128) {
        float v = 0;
        #pragma unroll
        for (int s = 0; s < 8; s++) v += g_CFTP[s][n][i];
        fl[i] = v;
    }
    __syncthreads();
    float acc = b1[t];
    #pragma unroll 4
    for (int k = 0; k < 576; k++)
        acc = fmaf(fl[k], W1[(size_t)k*128 + t], acc);
    hb[t] = 0.5f*acc*(1.0f + erff(acc*0.70710678118654752f));
    __syncthreads();
    if (t < 32) {
        float a2 = b2[t];
        #pragma unroll 4
        for (int k = 0; k < 128; k++)
            a2 = fmaf(hb[k], W2[k*32 + t], a2);
        g_CORR[((n>>6)*32 + t)*64 + (n&63)] = a2*corr_scale[0];
    }
}

extern "C" void kernel_launch(void* const* d_in, const int* in_sizes, int n_in,
                              void* d_out, int out_size) {
    const float* x    = (const float*)d_in[0];
    const float* w1re = (const float*)d_in[1];
    const float* w1im = (const float*)d_in[2];
    const float* w2re = (const float*)d_in[3];
    const float* w2im = (const float*)d_in[4];
    const float* w3re = (const float*)d_in[5];
    const float* w3im = (const float*)d_in[6];
    const float* w4re = (const float*)d_in[7];
    const float* w4im = (const float*)d_in[8];
    const float* W1   = (const float*)d_in[9];
    const float* b1   = (const float*)d_in[10];
    const float* W2   = (const float*)d_in[11];
    const float* b2   = (const float*)d_in[12];
    const float* cs   = (const float*)d_in[13];
    float* out = (float*)d_out;

    static int smem_set = 0;
    const int mix_smem = 110592;
    if (!smem_set) {
        cudaFuncSetAttribute(k_mix, cudaFuncAttributeMaxDynamicSharedMemorySize, mix_smem);
        smem_set = 1;
    }

    k_ck1<<<256, 256>>>(x);
    k_ck2<<<256, 128>>>(W1, b1, W2, b2, cs);

    k_f1<<<4096, 128>>>(x);
    k_f23<<<1536, 320>>>();
    k_mix<<<576, 256, mix_smem>>>(w1re, w1im, w2re, w2im, w3re, w3im, w4re, w4im);
    k_i1<<<1536, 256>>>();
    k_i23<<<8192, 256>>>(out);
}